// round 2
// baseline (speedup 1.0000x reference)
#include <cuda_runtime.h>
#include <stdint.h>

#define N_NODES 100000
#define N_EDGES 1600000
#define D_FEAT  64

// Scratch: CSR row pointers derived from sorted COO rows. (device global — no allocs)
__device__ int g_row_ptr[N_NODES + 1];

// Kernel A: edge-parallel boundary fill. rows is sorted, so for each position e
// where the row id changes, fill row_ptr for all rows in (rows[e-1], rows[e]].
__global__ void build_row_ptr(const int* __restrict__ rows, int n_edges) {
    int e = blockIdx.x * blockDim.x + threadIdx.x;
    if (e >= n_edges) return;
    int r = rows[e];
    int prev = (e == 0) ? -1 : rows[e - 1];
    for (int rr = prev + 1; rr <= r; ++rr) {
        g_row_ptr[rr] = e;
    }
    if (e == n_edges - 1) {
        for (int rr = r + 1; rr <= N_NODES; ++rr) {
            g_row_ptr[rr] = n_edges;
        }
    }
}

// Kernel B: one warp per output row. Each lane accumulates a float2 slice
// (32 lanes * 8B = 256B = one full embed row, coalesced). Edges for a row are
// contiguous [row_ptr[r], row_ptr[r+1]). 2-edge unroll for memory-level
// parallelism against L2 latency.
__global__ void __launch_bounds__(256) spmm_warp_per_row(
    const int*   __restrict__ cols,
    const float* __restrict__ vals,
    const float* __restrict__ embeds,
    float*       __restrict__ out)
{
    int gwarp = (blockIdx.x * blockDim.x + threadIdx.x) >> 5;
    int lane  = threadIdx.x & 31;
    if (gwarp >= N_NODES) return;

    int lo = g_row_ptr[gwarp];
    int hi = g_row_ptr[gwarp + 1];

    const float2* __restrict__ emb2 = reinterpret_cast<const float2*>(embeds);

    float ax = 0.f, ay = 0.f;
    float bx = 0.f, by = 0.f;

    int e = lo;
    for (; e + 1 < hi; e += 2) {
        int c0 = cols[e];
        int c1 = cols[e + 1];
        float v0 = vals[e];
        float v1 = vals[e + 1];
        float2 x0 = emb2[(long long)c0 * 32 + lane];
        float2 x1 = emb2[(long long)c1 * 32 + lane];
        ax += v0 * x0.x;  ay += v0 * x0.y;
        bx += v1 * x1.x;  by += v1 * x1.y;
    }
    if (e < hi) {
        int c0 = cols[e];
        float v0 = vals[e];
        float2 x0 = emb2[(long long)c0 * 32 + lane];
        ax += v0 * x0.x;  ay += v0 * x0.y;
    }

    float2 r;
    r.x = ax + bx;
    r.y = ay + by;
    reinterpret_cast<float2*>(out)[(long long)gwarp * 32 + lane] = r;
}

extern "C" void kernel_launch(void* const* d_in, const int* in_sizes, int n_in,
                              void* d_out, int out_size) {
    const int*   rows   = (const int*)d_in[0];
    const int*   cols   = (const int*)d_in[1];
    const float* vals   = (const float*)d_in[2];
    const float* embeds = (const float*)d_in[3];
    float*       out    = (float*)d_out;

    int n_edges = in_sizes[0];

    {
        int threads = 256;
        int blocks = (n_edges + threads - 1) / threads;
        build_row_ptr<<<blocks, threads>>>(rows, n_edges);
    }
    {
        // one warp per row: 100000 warps, 8 warps per block
        int threads = 256;
        int blocks = (N_NODES * 32 + threads - 1) / threads;
        spmm_warp_per_row<<<blocks, threads>>>(cols, vals, embeds, out);
    }
}

// round 3
// speedup vs baseline: 1.0520x; 1.0520x over previous
#include <cuda_runtime.h>
#include <stdint.h>

#define N_NODES 100000
#define N_EDGES 1600000
#define D_FEAT  64

// Scratch: CSR row pointers derived from sorted COO rows.
__device__ int g_row_ptr[N_NODES + 1];

// Edge-parallel boundary fill (rows sorted).
__global__ void build_row_ptr(const int* __restrict__ rows, int n_edges) {
    int e = blockIdx.x * blockDim.x + threadIdx.x;
    if (e >= n_edges) return;
    int r = rows[e];
    int prev = (e == 0) ? -1 : rows[e - 1];
    for (int rr = prev + 1; rr <= r; ++rr) {
        g_row_ptr[rr] = e;
    }
    if (e == n_edges - 1) {
        for (int rr = r + 1; rr <= N_NODES; ++rr) {
            g_row_ptr[rr] = n_edges;
        }
    }
}

// One warp per output row. float4 lanes: 16 lanes cover one 256B embed row,
// so the warp gathers TWO edges per instruction slot (half-warp per edge).
// Lanes 0-15 accumulate even-parity edges, 16-31 odd-parity; combined with a
// single shfl_down(16) at the end. 2-pair unroll -> 4 edges / 2 outstanding
// LDG.128 per lane for MLP against L2 latency (~240cyc).
__global__ void __launch_bounds__(256) spmm_warp_per_row(
    const int*   __restrict__ cols,
    const float* __restrict__ vals,
    const float* __restrict__ embeds,
    float*       __restrict__ out)
{
    int gwarp = (blockIdx.x * blockDim.x + threadIdx.x) >> 5;
    int lane  = threadIdx.x & 31;
    if (gwarp >= N_NODES) return;

    int lo = g_row_ptr[gwarp];
    int hi = g_row_ptr[gwarp + 1];

    const int half = lane >> 4;    // which edge of the pair this lane serves
    const int slot = lane & 15;    // float4 feature slice [4*slot .. 4*slot+3]

    const float4* __restrict__ emb4 = reinterpret_cast<const float4*>(embeds);

    float4 acc0 = make_float4(0.f, 0.f, 0.f, 0.f);
    float4 acc1 = make_float4(0.f, 0.f, 0.f, 0.f);

    int e = lo;
    // main loop: 4 edges per iteration (2 pairs)
    for (; e + 3 < hi; e += 4) {
        int   c0 = cols[e + half];
        int   c1 = cols[e + 2 + half];
        float v0 = vals[e + half];
        float v1 = vals[e + 2 + half];
        float4 x0 = emb4[(long long)c0 * 16 + slot];
        float4 x1 = emb4[(long long)c1 * 16 + slot];
        acc0.x += v0 * x0.x;  acc0.y += v0 * x0.y;
        acc0.z += v0 * x0.z;  acc0.w += v0 * x0.w;
        acc1.x += v1 * x1.x;  acc1.y += v1 * x1.y;
        acc1.z += v1 * x1.z;  acc1.w += v1 * x1.w;
    }
    // remainder: up to 3 edges, processed pair-wise with predication
    for (; e < hi; e += 2) {
        int idx = e + half;
        if (idx < hi) {
            int   c = cols[idx];
            float v = vals[idx];
            float4 x = emb4[(long long)c * 16 + slot];
            acc0.x += v * x.x;  acc0.y += v * x.y;
            acc0.z += v * x.z;  acc0.w += v * x.w;
        }
    }

    acc0.x += acc1.x;  acc0.y += acc1.y;
    acc0.z += acc1.z;  acc0.w += acc1.w;

    // fold odd-parity half onto even-parity half
    acc0.x += __shfl_down_sync(0xffffffffu, acc0.x, 16);
    acc0.y += __shfl_down_sync(0xffffffffu, acc0.y, 16);
    acc0.z += __shfl_down_sync(0xffffffffu, acc0.z, 16);
    acc0.w += __shfl_down_sync(0xffffffffu, acc0.w, 16);

    if (half == 0) {
        reinterpret_cast<float4*>(out)[(long long)gwarp * 16 + slot] = acc0;
    }
}

extern "C" void kernel_launch(void* const* d_in, const int* in_sizes, int n_in,
                              void* d_out, int out_size) {
    const int*   rows   = (const int*)d_in[0];
    const int*   cols   = (const int*)d_in[1];
    const float* vals   = (const float*)d_in[2];
    const float* embeds = (const float*)d_in[3];
    float*       out    = (float*)d_out;

    int n_edges = in_sizes[0];

    {
        int threads = 256;
        int blocks = (n_edges + threads - 1) / threads;
        build_row_ptr<<<blocks, threads>>>(rows, n_edges);
    }
    {
        int threads = 256;
        int blocks = (N_NODES * 32 + threads - 1) / threads;
        spmm_warp_per_row<<<blocks, threads>>>(cols, vals, embeds, out);
    }
}